// round 1
// baseline (speedup 1.0000x reference)
#include <cuda_runtime.h>
#include <math.h>

#define BATCH 2
#define SEQ 2048
#define DMODEL 2048
#define NH 16
#define NKV 4
#define HD 128
#define BS (BATCH*SEQ)
#define KVD (NKV*HD)

// scratch (allocation-free rule: __device__ globals)
__device__ float g_q[(size_t)BS*DMODEL];
__device__ float g_k[(size_t)BS*KVD];
__device__ float g_v[(size_t)BS*KVD];
__device__ float g_y[(size_t)BS*DMODEL];
__device__ float g_cos[SEQ*64];
__device__ float g_sin[SEQ*64];

// ---------------------------------------------------------------------------
// RoPE table: double-precision angles, rounded to fp32 (closest to jax fp32)
// ---------------------------------------------------------------------------
__global__ void rope_table_kernel() {
    int i = threadIdx.x;      // 0..63 freq index
    int t = blockIdx.x;       // 0..SEQ-1 position
    double inv = exp(-((double)(2 * i) / 128.0) * log(10000.0));
    double a = (double)t * inv;
    g_cos[t * 64 + i] = (float)cos(a);
    g_sin[t * 64 + i] = (float)sin(a);
}

// ---------------------------------------------------------------------------
// SGEMM: C[M,N] = A[M,K] @ B[N,K]^T   (both row-major, K contiguous)
// 128x128 block tile, BK=16, 256 threads, 8x8 microtile
// ---------------------------------------------------------------------------
__global__ __launch_bounds__(256) void sgemm_nt(const float* __restrict__ A,
                                                const float* __restrict__ Bw,
                                                float* __restrict__ C,
                                                int M, int N, int K) {
    __shared__ float As[16][128];
    __shared__ float Bs[16][128];
    const int tid = threadIdx.x;
    const int bm = blockIdx.y * 128;
    const int bn = blockIdx.x * 128;
    const int tx = tid & 15, ty = tid >> 4;

    float acc[8][8];
#pragma unroll
    for (int i = 0; i < 8; i++)
#pragma unroll
        for (int j = 0; j < 8; j++) acc[i][j] = 0.f;

    for (int k0 = 0; k0 < K; k0 += 16) {
#pragma unroll
        for (int i = 0; i < 2; i++) {
            int idx = tid + i * 256;
            int row = idx >> 2;          // 0..127
            int c4 = (idx & 3) << 2;     // 0,4,8,12
            float4 a = *(const float4*)(A + (size_t)(bm + row) * K + k0 + c4);
            As[c4 + 0][row] = a.x; As[c4 + 1][row] = a.y;
            As[c4 + 2][row] = a.z; As[c4 + 3][row] = a.w;
            float4 b = *(const float4*)(Bw + (size_t)(bn + row) * K + k0 + c4);
            Bs[c4 + 0][row] = b.x; Bs[c4 + 1][row] = b.y;
            Bs[c4 + 2][row] = b.z; Bs[c4 + 3][row] = b.w;
        }
        __syncthreads();
#pragma unroll
        for (int k = 0; k < 16; k++) {
            float a[8], b[8];
            *(float4*)&a[0] = *(const float4*)&As[k][ty * 8];
            *(float4*)&a[4] = *(const float4*)&As[k][ty * 8 + 4];
            *(float4*)&b[0] = *(const float4*)&Bs[k][tx * 8];
            *(float4*)&b[4] = *(const float4*)&Bs[k][tx * 8 + 4];
#pragma unroll
            for (int i = 0; i < 8; i++)
#pragma unroll
                for (int j = 0; j < 8; j++) acc[i][j] += a[i] * b[j];
        }
        __syncthreads();
    }
#pragma unroll
    for (int i = 0; i < 8; i++) {
        float4 o0 = make_float4(acc[i][0], acc[i][1], acc[i][2], acc[i][3]);
        float4 o1 = make_float4(acc[i][4], acc[i][5], acc[i][6], acc[i][7]);
        float* cp = C + (size_t)(bm + ty * 8 + i) * N + bn + tx * 8;
        *(float4*)cp = o0;
        *(float4*)(cp + 4) = o1;
    }
}

// ---------------------------------------------------------------------------
// Fused per-head RMSNorm + RoPE (+ q_gain * softmax scale for Q)
// grid (token, head), 128 threads = head_dim
// ---------------------------------------------------------------------------
__global__ __launch_bounds__(128) void rmsnorm_rope_kernel(float* __restrict__ data,
                                                           const float* __restrict__ gain,
                                                           int nheads, float outscale) {
    int token = blockIdx.x;        // 0..BS-1
    int h = blockIdx.y;
    int d = threadIdx.x;           // 0..127
    int s = token & (SEQ - 1);     // position within sequence
    float* row = data + ((size_t)token * nheads + h) * HD;
    float v = row[d];

    float ss = v * v;
#pragma unroll
    for (int o = 16; o; o >>= 1) ss += __shfl_xor_sync(0xffffffffu, ss, o);
    __shared__ float ws[4];
    int lane = d & 31, w = d >> 5;
    if (lane == 0) ws[w] = ss;
    __syncthreads();
    float tot = ws[0] + ws[1] + ws[2] + ws[3];
    float inv = rsqrtf(tot * (1.0f / HD) + 1.1920928955078125e-7f);
    v *= inv;

    __shared__ float sv[HD];
    sv[d] = v;
    __syncthreads();

    float out;
    if (d < 64) {
        float c = g_cos[s * 64 + d], si = g_sin[s * 64 + d];
        out = v * c + sv[d + 64] * si;
    } else {
        int i = d - 64;
        float c = g_cos[s * 64 + i], si = g_sin[s * 64 + i];
        out = -sv[i] * si + v * c;
    }
    if (gain) out *= gain[h] * outscale;
    row[d] = out;
}

// ---------------------------------------------------------------------------
// Flash attention (causal, GQA). Block = 256 threads = 8 warps;
// each warp owns 2 consecutive queries; 16 queries / block; 32-key tiles.
// Softmax scale pre-folded into Q.
// ---------------------------------------------------------------------------
__device__ __forceinline__ float warpmax_f(float v) {
#pragma unroll
    for (int o = 16; o; o >>= 1) v = fmaxf(v, __shfl_xor_sync(0xffffffffu, v, o));
    return v;
}
__device__ __forceinline__ float warpsum_f(float v) {
#pragma unroll
    for (int o = 16; o; o >>= 1) v += __shfl_xor_sync(0xffffffffu, v, o);
    return v;
}

__global__ __launch_bounds__(256) void flash_kernel(const float* __restrict__ q,
                                                    const float* __restrict__ k,
                                                    const float* __restrict__ v,
                                                    float* __restrict__ y) {
    __shared__ float Qs[16][128];
    __shared__ float Ks[32][132];   // padded for conflict-free float4
    __shared__ float Vs[32][132];

    int bh = blockIdx.y;
    int b = bh >> 4;               // / NH
    int h = bh & 15;
    int hkv = h >> 2;              // / (NH/NKV)
    int qbase = blockIdx.x * 16;
    int tid = threadIdx.x, lane = tid & 31, w = tid >> 5;

#pragma unroll
    for (int i = 0; i < 2; i++) {
        int idx = tid + i * 256;
        int row = idx >> 5;          // 0..15
        int c4 = (idx & 31) << 2;
        *(float4*)&Qs[row][c4] =
            *(const float4*)(q + ((size_t)(b * SEQ + qbase + row) * NH + h) * HD + c4);
    }

    int q0 = qbase + w * 2, q1 = q0 + 1;
    float m0 = -1e30f, m1 = -1e30f, l0 = 0.f, l1 = 0.f;
    float4 acc0 = make_float4(0, 0, 0, 0), acc1 = make_float4(0, 0, 0, 0);

    int ntiles = (qbase + 15) / 32 + 1;
    for (int kt = 0; kt < ntiles; kt++) {
        __syncthreads();
#pragma unroll
        for (int i = 0; i < 4; i++) {
            int idx = tid + i * 256;
            int row = idx >> 5;        // 0..31
            int c4 = (idx & 31) << 2;
            size_t gi = ((size_t)(b * SEQ + kt * 32 + row) * NKV + hkv) * HD + c4;
            *(float4*)&Ks[row][c4] = *(const float4*)(k + gi);
            *(float4*)&Vs[row][c4] = *(const float4*)(v + gi);
        }
        __syncthreads();

        float s0 = 0.f, s1 = 0.f;
#pragma unroll
        for (int d4 = 0; d4 < 32; d4++) {
            float4 kk = *(const float4*)&Ks[lane][d4 << 2];
            float4 qa = *(const float4*)&Qs[w * 2][d4 << 2];
            float4 qb = *(const float4*)&Qs[w * 2 + 1][d4 << 2];
            s0 += kk.x * qa.x + kk.y * qa.y + kk.z * qa.z + kk.w * qa.w;
            s1 += kk.x * qb.x + kk.y * qb.y + kk.z * qb.z + kk.w * qb.w;
        }
        int kidx = kt * 32 + lane;
        if (kidx > q0) s0 = -1e30f;
        if (kidx > q1) s1 = -1e30f;

        float mn0 = fmaxf(m0, warpmax_f(s0));
        float mn1 = fmaxf(m1, warpmax_f(s1));
        float p0 = __expf(s0 - mn0);
        float p1 = __expf(s1 - mn1);
        float c0 = __expf(m0 - mn0);
        float c1 = __expf(m1 - mn1);
        l0 = l0 * c0 + warpsum_f(p0);
        l1 = l1 * c1 + warpsum_f(p1);
        acc0.x *= c0; acc0.y *= c0; acc0.z *= c0; acc0.w *= c0;
        acc1.x *= c1; acc1.y *= c1; acc1.z *= c1; acc1.w *= c1;
        m0 = mn0; m1 = mn1;

#pragma unroll
        for (int j = 0; j < 32; j++) {
            float pj0 = __shfl_sync(0xffffffffu, p0, j);
            float pj1 = __shfl_sync(0xffffffffu, p1, j);
            float4 vv = *(const float4*)&Vs[j][lane << 2];
            acc0.x += pj0 * vv.x; acc0.y += pj0 * vv.y;
            acc0.z += pj0 * vv.z; acc0.w += pj0 * vv.w;
            acc1.x += pj1 * vv.x; acc1.y += pj1 * vv.y;
            acc1.z += pj1 * vv.z; acc1.w += pj1 * vv.w;
        }
    }

    float i0 = 1.f / l0, i1 = 1.f / l1;
    float4 o0 = make_float4(acc0.x * i0, acc0.y * i0, acc0.z * i0, acc0.w * i0);
    float4 o1 = make_float4(acc1.x * i1, acc1.y * i1, acc1.z * i1, acc1.w * i1);
    *(float4*)(y + ((size_t)(b * SEQ + q0) * NH + h) * HD + lane * 4) = o0;
    *(float4*)(y + ((size_t)(b * SEQ + q1) * NH + h) * HD + lane * 4) = o1;
}

// ---------------------------------------------------------------------------
extern "C" void kernel_launch(void* const* d_in, const int* in_sizes, int n_in,
                              void* d_out, int out_size) {
    const float* x     = (const float*)d_in[0];
    const float* Wq    = (const float*)d_in[1];
    const float* Wk    = (const float*)d_in[2];
    const float* Wv    = (const float*)d_in[3];
    const float* Wproj = (const float*)d_in[4];
    const float* qgain = (const float*)d_in[5];

    float *qb, *kb, *vb, *yb;
    cudaGetSymbolAddress((void**)&qb, g_q);
    cudaGetSymbolAddress((void**)&kb, g_k);
    cudaGetSymbolAddress((void**)&vb, g_v);
    cudaGetSymbolAddress((void**)&yb, g_y);

    rope_table_kernel<<<SEQ, 64>>>();

    sgemm_nt<<<dim3(DMODEL / 128, BS / 128), 256>>>(x, Wq, qb, BS, DMODEL, DMODEL);
    sgemm_nt<<<dim3(KVD / 128, BS / 128), 256>>>(x, Wk, kb, BS, KVD, DMODEL);
    sgemm_nt<<<dim3(KVD / 128, BS / 128), 256>>>(x, Wv, vb, BS, KVD, DMODEL);

    // q: gain * 1/sqrt(hd) folded in; k: plain norm+rope
    rmsnorm_rope_kernel<<<dim3(BS, NH), HD>>>(qb, qgain, NH, 0.08838834764831845f);
    rmsnorm_rope_kernel<<<dim3(BS, NKV), HD>>>(kb, nullptr, NKV, 1.0f);

    flash_kernel<<<dim3(SEQ / 16, BATCH * NH), 256>>>(qb, kb, vb, yb);

    sgemm_nt<<<dim3(DMODEL / 128, BS / 128), 256>>>(yb, Wproj, (float*)d_out, BS, DMODEL, DMODEL);
}

// round 3
// speedup vs baseline: 1.6984x; 1.6984x over previous
#include <cuda_runtime.h>
#include <cuda_bf16.h>
#include <math.h>
#include <stdint.h>

#define BATCH 2
#define SEQ 2048
#define DMODEL 2048
#define NH 16
#define NKV 4
#define HD 128
#define BS (BATCH*SEQ)
#define KVD (NKV*HD)

// ---------------- scratch (__device__ globals; no allocs allowed) ----------
__device__ float g_q[(size_t)BS*DMODEL];
__device__ float g_k[(size_t)BS*KVD];
__device__ float g_v[(size_t)BS*KVD];
__device__ float g_y[(size_t)BS*DMODEL];
__device__ float g_cos[SEQ*64];
__device__ float g_sin[SEQ*64];

__device__ __nv_bfloat16 g_xhi[(size_t)BS*DMODEL];
__device__ __nv_bfloat16 g_xlo[(size_t)BS*DMODEL];
__device__ __nv_bfloat16 g_yhi[(size_t)BS*DMODEL];
__device__ __nv_bfloat16 g_ylo[(size_t)BS*DMODEL];
__device__ __nv_bfloat16 g_wqhi[(size_t)DMODEL*DMODEL];
__device__ __nv_bfloat16 g_wqlo[(size_t)DMODEL*DMODEL];
__device__ __nv_bfloat16 g_wkhi[(size_t)KVD*DMODEL];
__device__ __nv_bfloat16 g_wklo[(size_t)KVD*DMODEL];
__device__ __nv_bfloat16 g_wvhi[(size_t)KVD*DMODEL];
__device__ __nv_bfloat16 g_wvlo[(size_t)KVD*DMODEL];
__device__ __nv_bfloat16 g_wphi[(size_t)DMODEL*DMODEL];
__device__ __nv_bfloat16 g_wplo[(size_t)DMODEL*DMODEL];

// ---------------- mma.sync helpers (sm_80-class, compiles on sm_103) -------
__device__ __forceinline__ uint32_t smem_u32(const void* p) {
    uint32_t a;
    asm("{ .reg .u64 t; cvta.to.shared.u64 t, %1; cvt.u32.u64 %0, t; }" : "=r"(a) : "l"(p));
    return a;
}
__device__ __forceinline__ void ldsm_x4(uint32_t* r, uint32_t addr) {
    asm volatile("ldmatrix.sync.aligned.m8n8.x4.shared.b16 {%0,%1,%2,%3}, [%4];"
                 : "=r"(r[0]), "=r"(r[1]), "=r"(r[2]), "=r"(r[3]) : "r"(addr));
}
__device__ __forceinline__ void mma_bf16(float* d, const uint32_t* a, const uint32_t* b) {
    asm volatile("mma.sync.aligned.m16n8k16.row.col.f32.bf16.bf16.f32 "
                 "{%0,%1,%2,%3}, {%4,%5,%6,%7}, {%8,%9}, {%0,%1,%2,%3};"
                 : "+f"(d[0]), "+f"(d[1]), "+f"(d[2]), "+f"(d[3])
                 : "r"(a[0]), "r"(a[1]), "r"(a[2]), "r"(a[3]), "r"(b[0]), "r"(b[1]));
}

// ---------------- fp32 -> bf16 hi/lo split ---------------------------------
__global__ __launch_bounds__(256) void split_kernel(const float4* __restrict__ src,
                                                    __nv_bfloat162* __restrict__ hi,
                                                    __nv_bfloat162* __restrict__ lo,
                                                    int n4) {
    int i = blockIdx.x * blockDim.x + threadIdx.x;
    if (i >= n4) return;
    float4 v = src[i];
    __nv_bfloat16 h0 = __float2bfloat16(v.x), h1 = __float2bfloat16(v.y);
    __nv_bfloat16 h2 = __float2bfloat16(v.z), h3 = __float2bfloat16(v.w);
    hi[2 * i + 0] = __halves2bfloat162(h0, h1);
    hi[2 * i + 1] = __halves2bfloat162(h2, h3);
    lo[2 * i + 0] = __halves2bfloat162(__float2bfloat16(v.x - __bfloat162float(h0)),
                                       __float2bfloat16(v.y - __bfloat162float(h1)));
    lo[2 * i + 1] = __halves2bfloat162(__float2bfloat16(v.z - __bfloat162float(h2)),
                                       __float2bfloat16(v.w - __bfloat162float(h3)));
}

// ---------------- bf16x3 mma.sync GEMM: C[M,N] = A[M,K] @ B[N,K]^T ---------
// 128x128 CTA tile, BK=32, 4-stage cp.async pipeline, 256 threads (8 warps 2x4)
#define GSTAGES 4
#define GBK 32
#define GTILEB (128*GBK*2)          // 8KB per tile
#define GSTAGEB (4*GTILEB)          // Ahi Alo Bhi Blo = 32KB
#define GSMEM_TOTAL (GSTAGES*GSTAGEB)

// swizzled byte offset inside a [128 x 32bf16] tile: row*64B + 16B chunks
__device__ __forceinline__ uint32_t sw_off(int row, int chunk) {
    return (uint32_t)(row * 64 + ((chunk ^ (row & 3)) << 4));
}
__device__ __forceinline__ void g_load_stage(const __nv_bfloat16* Ahi, const __nv_bfloat16* Alo,
                                             const __nv_bfloat16* Bhi, const __nv_bfloat16* Blo,
                                             int bm, int bn, int K, int kc,
                                             uint32_t tb, int tid) {
    size_t kcol = (size_t)kc * GBK;
#pragma unroll
    for (int j = 0; j < 2; j++) {
        int idx = tid + j * 256;
        int row = idx >> 2, c = idx & 3;
        uint32_t so = sw_off(row, c);
        size_t ga = (size_t)(bm + row) * K + kcol + c * 8;
        size_t gb = (size_t)(bn + row) * K + kcol + c * 8;
        asm volatile("cp.async.cg.shared.global [%0], [%1], 16;" :: "r"(tb + so), "l"(Ahi + ga));
        asm volatile("cp.async.cg.shared.global [%0], [%1], 16;" :: "r"(tb + GTILEB + so), "l"(Alo + ga));
        asm volatile("cp.async.cg.shared.global [%0], [%1], 16;" :: "r"(tb + 2 * GTILEB + so), "l"(Bhi + gb));
        asm volatile("cp.async.cg.shared.global [%0], [%1], 16;" :: "r"(tb + 3 * GTILEB + so), "l"(Blo + gb));
    }
}

__global__ __launch_bounds__(256, 1) void gemm_bf16x3(
    const __nv_bfloat16* __restrict__ Ahi, const __nv_bfloat16* __restrict__ Alo,
    const __nv_bfloat16* __restrict__ Bhi, const __nv_bfloat16* __restrict__ Blo,
    float* __restrict__ C, int M, int N, int K) {
    extern __shared__ char smem[];
    uint32_t sb = smem_u32(smem);
    int tid = threadIdx.x, wid = tid >> 5, lane = tid & 31;
    int bm = blockIdx.y * 128, bn = blockIdx.x * 128;
    int wm = (wid >> 2) * 64;       // 0 or 64
    int wn = (wid & 3) * 32;        // 0,32,64,96
    const int NK = K / GBK;

    float acc[4][4][4];
#pragma unroll
    for (int a = 0; a < 4; a++)
#pragma unroll
        for (int b = 0; b < 4; b++)
#pragma unroll
            for (int c = 0; c < 4; c++) acc[a][b][c] = 0.f;

    // prologue: fill stages 0..2
#pragma unroll
    for (int s = 0; s < GSTAGES - 1; s++) {
        g_load_stage(Ahi, Alo, Bhi, Blo, bm, bn, K, s, sb + s * GSTAGEB, tid);
        asm volatile("cp.async.commit_group;" ::: "memory");
    }

    for (int kc = 0; kc < NK; kc++) {
        asm volatile("cp.async.wait_group %0;" :: "n"(GSTAGES - 2) : "memory");
        __syncthreads();
        uint32_t tb = sb + (kc % GSTAGES) * GSTAGEB;

#pragma unroll
        for (int ks = 0; ks < 2; ks++) {
            uint32_t ah[4][4], al[4][4], bh[2][4], bl[2][4];
#pragma unroll
            for (int mt = 0; mt < 4; mt++) {
                int row = wm + mt * 16 + (lane & 15);
                uint32_t off = sw_off(row, ks * 2 + (lane >> 4));
                ldsm_x4(ah[mt], tb + off);
                ldsm_x4(al[mt], tb + GTILEB + off);
            }
#pragma unroll
            for (int pr = 0; pr < 2; pr++) {
                int row = wn + pr * 16 + (lane & 7) + ((lane >> 4) << 3);
                uint32_t off = sw_off(row, ks * 2 + ((lane >> 3) & 1));
                ldsm_x4(bh[pr], tb + 2 * GTILEB + off);
                ldsm_x4(bl[pr], tb + 3 * GTILEB + off);
            }
#pragma unroll
            for (int mt = 0; mt < 4; mt++)
#pragma unroll
                for (int nt = 0; nt < 4; nt++) {
                    const uint32_t* bhp = &bh[nt >> 1][(nt & 1) * 2];
                    const uint32_t* blp = &bl[nt >> 1][(nt & 1) * 2];
                    mma_bf16(acc[mt][nt], ah[mt], bhp);
                    mma_bf16(acc[mt][nt], ah[mt], blp);
                    mma_bf16(acc[mt][nt], al[mt], bhp);
                }
        }
        __syncthreads();
        if (kc + GSTAGES - 1 < NK) {
            int pst = (kc + GSTAGES - 1) % GSTAGES;
            g_load_stage(Ahi, Alo, Bhi, Blo, bm, bn, K, kc + GSTAGES - 1, sb + pst * GSTAGEB, tid);
        }
        asm volatile("cp.async.commit_group;" ::: "memory");
    }

    // epilogue
#pragma unroll
    for (int mt = 0; mt < 4; mt++) {
        int row0 = bm + wm + mt * 16 + (lane >> 2);
#pragma unroll
        for (int nt = 0; nt < 4; nt++) {
            int col = bn + wn + nt * 8 + (lane & 3) * 2;
            *(float2*)(C + (size_t)row0 * N + col) = make_float2(acc[mt][nt][0], acc[mt][nt][1]);
            *(float2*)(C + (size_t)(row0 + 8) * N + col) = make_float2(acc[mt][nt][2], acc[mt][nt][3]);
        }
    }
}

// ---------------- RoPE table ------------------------------------------------
__global__ void rope_table_kernel() {
    int i = threadIdx.x;
    int t = blockIdx.x;
    double inv = exp(-((double)(2 * i) / 128.0) * log(10000.0));
    double a = (double)t * inv;
    g_cos[t * 64 + i] = (float)cos(a);
    g_sin[t * 64 + i] = (float)sin(a);
}

// ---------------- fused RMSNorm + RoPE (+gain*scale for Q) ------------------
__global__ __launch_bounds__(128) void rmsnorm_rope_kernel(float* __restrict__ data,
                                                           const float* __restrict__ gain,
                                                           int nheads, float outscale) {
    int token = blockIdx.x;
    int h = blockIdx.y;
    int d = threadIdx.x;
    int s = token & (SEQ - 1);
    float* row = data + ((size_t)token * nheads + h) * HD;
    float v = row[d];

    float ss = v * v;
#pragma unroll
    for (int o = 16; o; o >>= 1) ss += __shfl_xor_sync(0xffffffffu, ss, o);
    __shared__ float ws[4];
    int lane = d & 31, w = d >> 5;
    if (lane == 0) ws[w] = ss;
    __syncthreads();
    float tot = ws[0] + ws[1] + ws[2] + ws[3];
    float inv = rsqrtf(tot * (1.0f / HD) + 1.1920928955078125e-7f);
    v *= inv;

    __shared__ float sv[HD];
    sv[d] = v;
    __syncthreads();

    float out;
    if (d < 64) {
        float c = g_cos[s * 64 + d], si = g_sin[s * 64 + d];
        out = v * c + sv[d + 64] * si;
    } else {
        int i = d - 64;
        float c = g_cos[s * 64 + i], si = g_sin[s * 64 + i];
        out = -sv[i] * si + v * c;
    }
    if (gain) out *= gain[h] * outscale;
    row[d] = out;
}

// ---------------- flash attention (causal, GQA), 4 queries per warp ---------
__device__ __forceinline__ float warpmax_f(float v) {
#pragma unroll
    for (int o = 16; o; o >>= 1) v = fmaxf(v, __shfl_xor_sync(0xffffffffu, v, o));
    return v;
}
__device__ __forceinline__ float warpsum_f(float v) {
#pragma unroll
    for (int o = 16; o; o >>= 1) v += __shfl_xor_sync(0xffffffffu, v, o);
    return v;
}

#define FQ 32
#define FSMEM (4096*4 + 2*4224*4)

__global__ __launch_bounds__(256) void flash_kernel(const float* __restrict__ q,
                                                    const float* __restrict__ k,
                                                    const float* __restrict__ v,
                                                    float* __restrict__ y) {
    extern __shared__ float fsm[];
    float* Qs = fsm;               // [32][128]
    float* Ks = fsm + 4096;        // [32][132]
    float* Vs = fsm + 4096 + 4224; // [32][132]

    int bh = blockIdx.y;
    int b = bh >> 4;
    int h = bh & 15;
    int hkv = h >> 2;
    int qbase = blockIdx.x * FQ;
    int tid = threadIdx.x, lane = tid & 31, w = tid >> 5;

#pragma unroll
    for (int i = 0; i < 4; i++) {
        int idx = tid + i * 256;
        int row = idx >> 5;
        int c4 = (idx & 31) << 2;
        *(float4*)&Qs[row * 128 + c4] =
            *(const float4*)(q + ((size_t)(b * SEQ + qbase + row) * NH + h) * HD + c4);
    }

    int qw = qbase + w * 4;
    float m[4] = {-1e30f, -1e30f, -1e30f, -1e30f};
    float l[4] = {0.f, 0.f, 0.f, 0.f};
    float4 acc[4];
#pragma unroll
    for (int qi = 0; qi < 4; qi++) acc[qi] = make_float4(0, 0, 0, 0);

    int ntiles = (qbase + FQ - 1) / 32 + 1;
    for (int kt = 0; kt < ntiles; kt++) {
        __syncthreads();
#pragma unroll
        for (int i = 0; i < 4; i++) {
            int idx = tid + i * 256;
            int row = idx >> 5;
            int c4 = (idx & 31) << 2;
            size_t gi = ((size_t)(b * SEQ + kt * 32 + row) * NKV + hkv) * HD + c4;
            *(float4*)&Ks[row * 132 + c4] = *(const float4*)(k + gi);
            *(float4*)&Vs[row * 132 + c4] = *(const float4*)(v + gi);
        }
        __syncthreads();

        float s[4] = {0.f, 0.f, 0.f, 0.f};
#pragma unroll
        for (int d4 = 0; d4 < 32; d4++) {
            float4 kk = *(const float4*)&Ks[lane * 132 + (d4 << 2)];
#pragma unroll
            for (int qi = 0; qi < 4; qi++) {
                float4 qq = *(const float4*)&Qs[(w * 4 + qi) * 128 + (d4 << 2)];
                s[qi] += kk.x * qq.x + kk.y * qq.y + kk.z * qq.z + kk.w * qq.w;
            }
        }
        int kidx = kt * 32 + lane;
        float p[4];
#pragma unroll
        for (int qi = 0; qi < 4; qi++) {
            if (kidx > qw + qi) s[qi] = -1e30f;
            float mn = fmaxf(m[qi], warpmax_f(s[qi]));
            p[qi] = __expf(s[qi] - mn);
            float c = __expf(m[qi] - mn);
            l[qi] = l[qi] * c + warpsum_f(p[qi]);
            acc[qi].x *= c; acc[qi].y *= c; acc[qi].z *= c; acc[qi].w *= c;
            m[qi] = mn;
        }

#pragma unroll
        for (int j = 0; j < 32; j++) {
            float4 vv = *(const float4*)&Vs[j * 132 + (lane << 2)];
#pragma unroll
            for (int qi = 0; qi < 4; qi++) {
                float pj = __shfl_sync(0xffffffffu, p[qi], j);
                acc[qi].x += pj * vv.x; acc[qi].y += pj * vv.y;
                acc[qi].z += pj * vv.z; acc[qi].w += pj * vv.w;
            }
        }
    }

#pragma unroll
    for (int qi = 0; qi < 4; qi++) {
        float iv = 1.f / l[qi];
        float4 o = make_float4(acc[qi].x * iv, acc[qi].y * iv, acc[qi].z * iv, acc[qi].w * iv);
        *(float4*)(y + ((size_t)(b * SEQ + qw + qi) * NH + h) * HD + lane * 4) = o;
    }
}

// ---------------------------------------------------------------------------
extern "C" void kernel_launch(void* const* d_in, const int* in_sizes, int n_in,
                              void* d_out, int out_size) {
    const float* x     = (const float*)d_in[0];
    const float* Wq    = (const float*)d_in[1];
    const float* Wk    = (const float*)d_in[2];
    const float* Wv    = (const float*)d_in[3];
    const float* Wproj = (const float*)d_in[4];
    const float* qgain = (const float*)d_in[5];

    float *qb, *kb, *vb, *yb;
    cudaGetSymbolAddress((void**)&qb, g_q);
    cudaGetSymbolAddress((void**)&kb, g_k);
    cudaGetSymbolAddress((void**)&vb, g_v);
    cudaGetSymbolAddress((void**)&yb, g_y);
    __nv_bfloat16 *xhi, *xlo, *yhi, *ylo, *wqh, *wql, *wkh, *wkl, *wvh, *wvl, *wph, *wpl;
    cudaGetSymbolAddress((void**)&xhi, g_xhi);  cudaGetSymbolAddress((void**)&xlo, g_xlo);
    cudaGetSymbolAddress((void**)&yhi, g_yhi);  cudaGetSymbolAddress((void**)&ylo, g_ylo);
    cudaGetSymbolAddress((void**)&wqh, g_wqhi); cudaGetSymbolAddress((void**)&wql, g_wqlo);
    cudaGetSymbolAddress((void**)&wkh, g_wkhi); cudaGetSymbolAddress((void**)&wkl, g_wklo);
    cudaGetSymbolAddress((void**)&wvh, g_wvhi); cudaGetSymbolAddress((void**)&wvl, g_wvlo);
    cudaGetSymbolAddress((void**)&wph, g_wphi); cudaGetSymbolAddress((void**)&wpl, g_wplo);

    cudaFuncSetAttribute(gemm_bf16x3, cudaFuncAttributeMaxDynamicSharedMemorySize, GSMEM_TOTAL);
    cudaFuncSetAttribute(flash_kernel, cudaFuncAttributeMaxDynamicSharedMemorySize, FSMEM);

    rope_table_kernel<<<SEQ, 64>>>();

    {
        int n4 = BS * DMODEL / 4;
        split_kernel<<<(n4 + 255) / 256, 256>>>((const float4*)x, (__nv_bfloat162*)xhi, (__nv_bfloat162*)xlo, n4);
        n4 = DMODEL * DMODEL / 4;
        split_kernel<<<(n4 + 255) / 256, 256>>>((const float4*)Wq, (__nv_bfloat162*)wqh, (__nv_bfloat162*)wql, n4);
        split_kernel<<<(n4 + 255) / 256, 256>>>((const float4*)Wproj, (__nv_bfloat162*)wph, (__nv_bfloat162*)wpl, n4);
        n4 = KVD * DMODEL / 4;
        split_kernel<<<(n4 + 255) / 256, 256>>>((const float4*)Wk, (__nv_bfloat162*)wkh, (__nv_bfloat162*)wkl, n4);
        split_kernel<<<(n4 + 255) / 256, 256>>>((const float4*)Wv, (__nv_bfloat162*)wvh, (__nv_bfloat162*)wvl, n4);
    }

    gemm_bf16x3<<<dim3(DMODEL / 128, BS / 128), 256, GSMEM_TOTAL>>>(xhi, xlo, wqh, wql, qb, BS, DMODEL, DMODEL);
    gemm_bf16x3<<<dim3(KVD / 128, BS / 128), 256, GSMEM_TOTAL>>>(xhi, xlo, wkh, wkl, kb, BS, KVD, DMODEL);
    gemm_bf16x3<<<dim3(KVD / 128, BS / 128), 256, GSMEM_TOTAL>>>(xhi, xlo, wvh, wvl, vb, BS, KVD, DMODEL);

    rmsnorm_rope_kernel<<<dim3(BS, NH), HD>>>(qb, qgain, NH, 0.08838834764831845f);
    rmsnorm_rope_kernel<<<dim3(BS, NKV), HD>>>(kb, nullptr, NKV, 1.0f);

    flash_kernel<<<dim3(SEQ / FQ, BATCH * NH), 256, FSMEM>>>(qb, kb, vb, yb);

    {
        int n4 = BS * DMODEL / 4;
        split_kernel<<<(n4 + 255) / 256, 256>>>((const float4*)yb, (__nv_bfloat162*)yhi, (__nv_bfloat162*)ylo, n4);
    }
    gemm_bf16x3<<<dim3(DMODEL / 128, BS / 128), 256, GSMEM_TOTAL>>>(yhi, ylo, wph, wpl, (float*)d_out, BS, DMODEL, DMODEL);
}

// round 5
// speedup vs baseline: 2.1961x; 1.2930x over previous
#include <cuda_runtime.h>
#include <cuda_bf16.h>
#include <math.h>
#include <stdint.h>
#include <string.h>

#define BATCH 2
#define SEQ 2048
#define DMODEL 2048
#define NH 16
#define NKV 4
#define HD 128
#define BS (BATCH*SEQ)
#define KVD (NKV*HD)
#define LOG2E 1.4426950408889634f

// ---------------- scratch (__device__ globals; no allocs allowed) ----------
__device__ float g_q[(size_t)BS*DMODEL];
__device__ float g_k[(size_t)BS*KVD];
__device__ float g_v[(size_t)BS*KVD];
__device__ float g_cos[SEQ*64];
__device__ float g_sin[SEQ*64];

__device__ __nv_bfloat16 g_xhi[(size_t)BS*DMODEL];
__device__ __nv_bfloat16 g_xlo[(size_t)BS*DMODEL];
__device__ __nv_bfloat16 g_yhi[(size_t)BS*DMODEL];
__device__ __nv_bfloat16 g_ylo[(size_t)BS*DMODEL];
__device__ __nv_bfloat16 g_qhi[(size_t)BS*DMODEL];
__device__ __nv_bfloat16 g_qlo[(size_t)BS*DMODEL];
__device__ __nv_bfloat16 g_khi[(size_t)BS*KVD];
__device__ __nv_bfloat16 g_klo[(size_t)BS*KVD];
__device__ __nv_bfloat16 g_vhi[(size_t)BS*KVD];
__device__ __nv_bfloat16 g_vlo[(size_t)BS*KVD];
__device__ __nv_bfloat16 g_wqhi[(size_t)DMODEL*DMODEL];
__device__ __nv_bfloat16 g_wqlo[(size_t)DMODEL*DMODEL];
__device__ __nv_bfloat16 g_wkhi[(size_t)KVD*DMODEL];
__device__ __nv_bfloat16 g_wklo[(size_t)KVD*DMODEL];
__device__ __nv_bfloat16 g_wvhi[(size_t)KVD*DMODEL];
__device__ __nv_bfloat16 g_wvlo[(size_t)KVD*DMODEL];
__device__ __nv_bfloat16 g_wphi[(size_t)DMODEL*DMODEL];
__device__ __nv_bfloat16 g_wplo[(size_t)DMODEL*DMODEL];

// ---------------- mma.sync helpers -----------------------------------------
__device__ __forceinline__ uint32_t smem_u32(const void* p) {
    uint32_t a;
    asm("{ .reg .u64 t; cvta.to.shared.u64 t, %1; cvt.u32.u64 %0, t; }" : "=r"(a) : "l"(p));
    return a;
}
__device__ __forceinline__ void ldsm_x4(uint32_t* r, uint32_t addr) {
    asm volatile("ldmatrix.sync.aligned.m8n8.x4.shared.b16 {%0,%1,%2,%3}, [%4];"
                 : "=r"(r[0]), "=r"(r[1]), "=r"(r[2]), "=r"(r[3]) : "r"(addr));
}
__device__ __forceinline__ void ldsm_x4_t(uint32_t* r, uint32_t addr) {
    asm volatile("ldmatrix.sync.aligned.m8n8.x4.trans.shared.b16 {%0,%1,%2,%3}, [%4];"
                 : "=r"(r[0]), "=r"(r[1]), "=r"(r[2]), "=r"(r[3]) : "r"(addr));
}
__device__ __forceinline__ void mma_bf16(float* d, const uint32_t* a, const uint32_t* b) {
    asm volatile("mma.sync.aligned.m16n8k16.row.col.f32.bf16.bf16.f32 "
                 "{%0,%1,%2,%3}, {%4,%5,%6,%7}, {%8,%9}, {%0,%1,%2,%3};"
                 : "+f"(d[0]), "+f"(d[1]), "+f"(d[2]), "+f"(d[3])
                 : "r"(a[0]), "r"(a[1]), "r"(a[2]), "r"(a[3]), "r"(b[0]), "r"(b[1]));
}
// pack two floats into bf16x2 (v1 in high half, v0 in low half)
__device__ __forceinline__ uint32_t pack_bf16x2(float v0, float v1) {
    uint32_t r;
    asm("cvt.rn.bf16x2.f32 %0, %1, %2;" : "=r"(r) : "f"(v1), "f"(v0));
    return r;
}
#define CP_ASYNC16(s, g) \
    asm volatile("cp.async.cg.shared.global [%0], [%1], 16;" :: "r"(s), "l"(g))

// ---------------- fp32 -> bf16 hi/lo split ---------------------------------
__global__ __launch_bounds__(256) void split_kernel(const float4* __restrict__ src,
                                                    __nv_bfloat162* __restrict__ hi,
                                                    __nv_bfloat162* __restrict__ lo,
                                                    int n4) {
    int i = blockIdx.x * blockDim.x + threadIdx.x;
    if (i >= n4) return;
    float4 v = src[i];
    __nv_bfloat16 h0 = __float2bfloat16(v.x), h1 = __float2bfloat16(v.y);
    __nv_bfloat16 h2 = __float2bfloat16(v.z), h3 = __float2bfloat16(v.w);
    hi[2 * i + 0] = __halves2bfloat162(h0, h1);
    hi[2 * i + 1] = __halves2bfloat162(h2, h3);
    lo[2 * i + 0] = __halves2bfloat162(__float2bfloat16(v.x - __bfloat162float(h0)),
                                       __float2bfloat16(v.y - __bfloat162float(h1)));
    lo[2 * i + 1] = __halves2bfloat162(__float2bfloat16(v.z - __bfloat162float(h2)),
                                       __float2bfloat16(v.w - __bfloat162float(h3)));
}

// ---------------- bf16x3 mma.sync GEMM (validated in R3) -------------------
#define GSTAGES 4
#define GBK 32
#define GTILEB (128*GBK*2)
#define GSTAGEB (4*GTILEB)
#define GSMEM_TOTAL (GSTAGES*GSTAGEB)

__device__ __forceinline__ uint32_t sw_off(int row, int chunk) {
    return (uint32_t)(row * 64 + ((chunk ^ (row & 3)) << 4));
}
__device__ __forceinline__ void g_load_stage(const __nv_bfloat16* Ahi, const __nv_bfloat16* Alo,
                                             const __nv_bfloat16* Bhi, const __nv_bfloat16* Blo,
                                             int bm, int bn, int K, int kc,
                                             uint32_t tb, int tid) {
    size_t kcol = (size_t)kc * GBK;
#pragma unroll
    for (int j = 0; j < 2; j++) {
        int idx = tid + j * 256;
        int row = idx >> 2, c = idx & 3;
        uint32_t so = sw_off(row, c);
        size_t ga = (size_t)(bm + row) * K + kcol + c * 8;
        size_t gb = (size_t)(bn + row) * K + kcol + c * 8;
        CP_ASYNC16(tb + so, Ahi + ga);
        CP_ASYNC16(tb + GTILEB + so, Alo + ga);
        CP_ASYNC16(tb + 2 * GTILEB + so, Bhi + gb);
        CP_ASYNC16(tb + 3 * GTILEB + so, Blo + gb);
    }
}

__global__ __launch_bounds__(256, 1) void gemm_bf16x3(
    const __nv_bfloat16* __restrict__ Ahi, const __nv_bfloat16* __restrict__ Alo,
    const __nv_bfloat16* __restrict__ Bhi, const __nv_bfloat16* __restrict__ Blo,
    float* __restrict__ C, int M, int N, int K) {
    extern __shared__ char smem[];
    uint32_t sb = smem_u32(smem);
    int tid = threadIdx.x, wid = tid >> 5, lane = tid & 31;
    int bm = blockIdx.y * 128, bn = blockIdx.x * 128;
    int wm = (wid >> 2) * 64;
    int wn = (wid & 3) * 32;
    const int NK = K / GBK;

    float acc[4][4][4];
#pragma unroll
    for (int a = 0; a < 4; a++)
#pragma unroll
        for (int b = 0; b < 4; b++)
#pragma unroll
            for (int c = 0; c < 4; c++) acc[a][b][c] = 0.f;

#pragma unroll
    for (int s = 0; s < GSTAGES - 1; s++) {
        g_load_stage(Ahi, Alo, Bhi, Blo, bm, bn, K, s, sb + s * GSTAGEB, tid);
        asm volatile("cp.async.commit_group;" ::: "memory");
    }

    for (int kc = 0; kc < NK; kc++) {
        asm volatile("cp.async.wait_group %0;" :: "n"(GSTAGES - 2) : "memory");
        __syncthreads();
        uint32_t tb = sb + (kc % GSTAGES) * GSTAGEB;

#pragma unroll
        for (int ks = 0; ks < 2; ks++) {
            uint32_t ah[4][4], al[4][4], bh[2][4], bl[2][4];
#pragma unroll
            for (int mt = 0; mt < 4; mt++) {
                int row = wm + mt * 16 + (lane & 15);
                uint32_t off = sw_off(row, ks * 2 + (lane >> 4));
                ldsm_x4(ah[mt], tb + off);
                ldsm_x4(al[mt], tb + GTILEB + off);
            }
#pragma unroll
            for (int pr = 0; pr < 2; pr++) {
                int row = wn + pr * 16 + (lane & 7) + ((lane >> 4) << 3);
                uint32_t off = sw_off(row, ks * 2 + ((lane >> 3) & 1));
                ldsm_x4(bh[pr], tb + 2 * GTILEB + off);
                ldsm_x4(bl[pr], tb + 3 * GTILEB + off);
            }
#pragma unroll
            for (int mt = 0; mt < 4; mt++)
#pragma unroll
                for (int nt = 0; nt < 4; nt++) {
                    const uint32_t* bhp = &bh[nt >> 1][(nt & 1) * 2];
                    const uint32_t* blp = &bl[nt >> 1][(nt & 1) * 2];
                    mma_bf16(acc[mt][nt], ah[mt], bhp);
                    mma_bf16(acc[mt][nt], ah[mt], blp);
                    mma_bf16(acc[mt][nt], al[mt], bhp);
                }
        }
        __syncthreads();
        if (kc + GSTAGES - 1 < NK) {
            int pst = (kc + GSTAGES - 1) % GSTAGES;
            g_load_stage(Ahi, Alo, Bhi, Blo, bm, bn, K, kc + GSTAGES - 1, sb + pst * GSTAGEB, tid);
        }
        asm volatile("cp.async.commit_group;" ::: "memory");
    }

#pragma unroll
    for (int mt = 0; mt < 4; mt++) {
        int row0 = bm + wm + mt * 16 + (lane >> 2);
#pragma unroll
        for (int nt = 0; nt < 4; nt++) {
            int col = bn + wn + nt * 8 + (lane & 3) * 2;
            *(float2*)(C + (size_t)row0 * N + col) = make_float2(acc[mt][nt][0], acc[mt][nt][1]);
            *(float2*)(C + (size_t)(row0 + 8) * N + col) = make_float2(acc[mt][nt][2], acc[mt][nt][3]);
        }
    }
}

// ---------------- RoPE table ------------------------------------------------
__global__ void rope_table_kernel() {
    int i = threadIdx.x;
    int t = blockIdx.x;
    double inv = exp(-((double)(2 * i) / 128.0) * log(10000.0));
    double a = (double)t * inv;
    g_cos[t * 64 + i] = (float)cos(a);
    g_sin[t * 64 + i] = (float)sin(a);
}

// ---------------- fused RMSNorm + RoPE -> bf16 hi/lo ------------------------
__global__ __launch_bounds__(128) void rmsnorm_rope_split(const float* __restrict__ src,
                                                          __nv_bfloat16* __restrict__ dhi,
                                                          __nv_bfloat16* __restrict__ dlo,
                                                          const float* __restrict__ gain,
                                                          int nheads, float outscale) {
    int token = blockIdx.x;
    int h = blockIdx.y;
    int d = threadIdx.x;
    int s = token & (SEQ - 1);
    size_t idx = ((size_t)token * nheads + h) * HD + d;
    float v = src[idx];

    float ss = v * v;
#pragma unroll
    for (int o = 16; o; o >>= 1) ss += __shfl_xor_sync(0xffffffffu, ss, o);
    __shared__ float ws[4];
    int lane = d & 31, w = d >> 5;
    if (lane == 0) ws[w] = ss;
    __syncthreads();
    float tot = ws[0] + ws[1] + ws[2] + ws[3];
    float inv = rsqrtf(tot * (1.0f / HD) + 1.1920928955078125e-7f);
    v *= inv;

    __shared__ float sv[HD];
    sv[d] = v;
    __syncthreads();

    float out;
    if (d < 64) {
        float c = g_cos[s * 64 + d], si = g_sin[s * 64 + d];
        out = v * c + sv[d + 64] * si;
    } else {
        int i = d - 64;
        float c = g_cos[s * 64 + i], si = g_sin[s * 64 + i];
        out = -sv[i] * si + v * c;
    }
    if (gain) out *= gain[h] * outscale;
    __nv_bfloat16 hv = __float2bfloat16(out);
    dhi[idx] = hv;
    dlo[idx] = __float2bfloat16(out - __bfloat162float(hv));
}

// ---------------- tensor-core flash attention (causal, GQA, bf16x3) ---------
// Block: 128 queries, 8 warps (16 q each). KV tiles of 64 keys, double buffer.
#define FBQ 128
#define FBK 64
#define F_QHI 0
#define F_QLO 32768
#define F_STAGE0 65536
#define F_STAGEB 65536
#define F_KH 0
#define F_KL 16384
#define F_VH 32768
#define F_VL 49152
#define FSMEM_TOTAL (65536 + 2*F_STAGEB)

// swizzled offset inside a [rows][128] bf16 tile (256B rows, 16 chunks of 16B)
__device__ __forceinline__ uint32_t f_off(int row, int chunk) {
    return (uint32_t)(row * 256 + ((chunk ^ (row & 7)) << 4));
}

__device__ __forceinline__ void f_load_kv(uint32_t st,
                                          const __nv_bfloat16* kh, const __nv_bfloat16* kl,
                                          const __nv_bfloat16* vh, const __nv_bfloat16* vl,
                                          size_t gbase, int tid) {
#pragma unroll
    for (int j = 0; j < 4; j++) {
        int id = tid + j * 256;
        int row = id >> 4, c = id & 15;
        uint32_t so = f_off(row, c);
        size_t g = gbase + (size_t)row * KVD + c * 8;
        CP_ASYNC16(st + F_KH + so, kh + g);
        CP_ASYNC16(st + F_KL + so, kl + g);
        CP_ASYNC16(st + F_VH + so, vh + g);
        CP_ASYNC16(st + F_VL + so, vl + g);
    }
}

__global__ __launch_bounds__(256, 1) void flash_mma(
    const __nv_bfloat16* __restrict__ qh, const __nv_bfloat16* __restrict__ ql,
    const __nv_bfloat16* __restrict__ kh, const __nv_bfloat16* __restrict__ kl,
    const __nv_bfloat16* __restrict__ vh, const __nv_bfloat16* __restrict__ vl,
    __nv_bfloat16* __restrict__ yhi, __nv_bfloat16* __restrict__ ylo) {
    extern __shared__ char smem[];
    uint32_t sb = smem_u32(smem);
    int tid = threadIdx.x, lane = tid & 31, w = tid >> 5;
    int bh_ = blockIdx.y;
    int b = bh_ >> 4, h = bh_ & 15, hkv = h >> 2;
    int qb = blockIdx.x * FBQ;
    int q0 = w * 16;

    // ---- load Q (hi+lo) ----
#pragma unroll
    for (int j = 0; j < 8; j++) {
        int id = tid + j * 256;
        int row = id >> 4, c = id & 15;
        uint32_t so = f_off(row, c);
        size_t g = ((size_t)(b * SEQ + qb + row)) * DMODEL + h * HD + c * 8;
        CP_ASYNC16(sb + F_QHI + so, qh + g);
        CP_ASYNC16(sb + F_QLO + so, ql + g);
    }
    asm volatile("cp.async.commit_group;" ::: "memory");

    size_t kvhead = (size_t)(b * SEQ) * KVD + hkv * HD;
    int ntiles = qb / FBK + 2;

    f_load_kv(sb + F_STAGE0, kh, kl, vh, vl, kvhead, tid);
    asm volatile("cp.async.commit_group;" ::: "memory");

    float o[16][4];
#pragma unroll
    for (int nt = 0; nt < 16; nt++)
#pragma unroll
        for (int e = 0; e < 4; e++) o[nt][e] = 0.f;
    float m0 = -1e30f, m1 = -1e30f, l0 = 0.f, l1 = 0.f;

    int qmax = qb + q0 + 15;
    int rr0 = qb + q0 + (lane >> 2);
    int rr1 = rr0 + 8;

    for (int t = 0; t < ntiles; t++) {
        if (t + 1 < ntiles)
            f_load_kv(sb + F_STAGE0 + ((t + 1) & 1) * F_STAGEB, kh, kl, vh, vl,
                      kvhead + (size_t)(t + 1) * FBK * KVD, tid);
        asm volatile("cp.async.commit_group;" ::: "memory");
        asm volatile("cp.async.wait_group 1;" ::: "memory");
        __syncthreads();

        int kv = t * FBK;
        if (kv <= qmax) {
            uint32_t st = sb + F_STAGE0 + (t & 1) * F_STAGEB;

            // ---- S = Q K^T (bf16x3) ----
            float c[8][4];
#pragma unroll
            for (int nt = 0; nt < 8; nt++)
#pragma unroll
                for (int e = 0; e < 4; e++) c[nt][e] = 0.f;

#pragma unroll
            for (int ds = 0; ds < 8; ds++) {
                uint32_t qoff = f_off(q0 + (lane & 15), ds * 2 + (lane >> 4));
                uint32_t ah4[4], al4[4];
                ldsm_x4(ah4, sb + F_QHI + qoff);
                ldsm_x4(al4, sb + F_QLO + qoff);
                uint32_t bh4[4][4], bl4[4][4];
#pragma unroll
                for (int g = 0; g < 4; g++) {
                    int rowk = g * 16 + (lane & 7) + ((lane >> 4) << 3);
                    uint32_t koff = f_off(rowk, ds * 2 + ((lane >> 3) & 1));
                    ldsm_x4(bh4[g], st + F_KH + koff);
                    ldsm_x4(bl4[g], st + F_KL + koff);
                }
#pragma unroll
                for (int g = 0; g < 4; g++)
#pragma unroll
                    for (int sub = 0; sub < 2; sub++) {
                        int nt = g * 2 + sub;
                        mma_bf16(c[nt], ah4, &bh4[g][sub * 2]);
                        mma_bf16(c[nt], ah4, &bl4[g][sub * 2]);
                        mma_bf16(c[nt], al4, &bh4[g][sub * 2]);
                    }
            }

            // ---- causal mask ----
            if (kv + FBK - 1 > qb + q0) {
#pragma unroll
                for (int nt = 0; nt < 8; nt++) {
                    int col = kv + nt * 8 + (lane & 3) * 2;
                    if (col > rr0) c[nt][0] = -1e30f;
                    if (col + 1 > rr0) c[nt][1] = -1e30f;
                    if (col > rr1) c[nt][2] = -1e30f;
                    if (col + 1 > rr1) c[nt][3] = -1e30f;
                }
            }

            // ---- online softmax ----
            float mx0 = -1e30f, mx1 = -1e30f;
#pragma unroll
            for (int nt = 0; nt < 8; nt++) {
                mx0 = fmaxf(mx0, fmaxf(c[nt][0], c[nt][1]));
                mx1 = fmaxf(mx1, fmaxf(c[nt][2], c[nt][3]));
            }
            mx0 = fmaxf(mx0, __shfl_xor_sync(0xffffffffu, mx0, 1));
            mx0 = fmaxf(mx0, __shfl_xor_sync(0xffffffffu, mx0, 2));
            mx1 = fmaxf(mx1, __shfl_xor_sync(0xffffffffu, mx1, 1));
            mx1 = fmaxf(mx1, __shfl_xor_sync(0xffffffffu, mx1, 2));
            float m0n = fmaxf(m0, mx0), m1n = fmaxf(m1, mx1);
            float rs0 = exp2f((m0 - m0n) * LOG2E);
            float rs1 = exp2f((m1 - m1n) * LOG2E);
            float s0 = 0.f, s1 = 0.f;
#pragma unroll
            for (int nt = 0; nt < 8; nt++) {
                c[nt][0] = exp2f((c[nt][0] - m0n) * LOG2E);
                c[nt][1] = exp2f((c[nt][1] - m0n) * LOG2E);
                c[nt][2] = exp2f((c[nt][2] - m1n) * LOG2E);
                c[nt][3] = exp2f((c[nt][3] - m1n) * LOG2E);
                s0 += c[nt][0] + c[nt][1];
                s1 += c[nt][2] + c[nt][3];
            }
            s0 += __shfl_xor_sync(0xffffffffu, s0, 1);
            s0 += __shfl_xor_sync(0xffffffffu, s0, 2);
            s1 += __shfl_xor_sync(0xffffffffu, s1, 1);
            s1 += __shfl_xor_sync(0xffffffffu, s1, 2);
            l0 = l0 * rs0 + s0;
            l1 = l1 * rs1 + s1;
            m0 = m0n; m1 = m1n;
#pragma unroll
            for (int nt = 0; nt < 16; nt++) {
                o[nt][0] *= rs0; o[nt][1] *= rs0;
                o[nt][2] *= rs1; o[nt][3] *= rs1;
            }

            // ---- P (bf16 hi/lo A-frags) x V ----
#pragma unroll
            for (int kt = 0; kt < 4; kt++) {
                uint32_t aph[4], apl[4];
#pragma unroll
                for (int half = 0; half < 2; half++) {
                    const float* cc = c[2 * kt + half];
#pragma unroll
                    for (int rh = 0; rh < 2; rh++) {
                        float v0 = cc[rh * 2], v1 = cc[rh * 2 + 1];
                        uint32_t hp = pack_bf16x2(v0, v1);
                        __nv_bfloat162 hb;
                        memcpy(&hb, &hp, 4);
                        float r0 = v0 - __bfloat162float(__low2bfloat16(hb));
                        float r1 = v1 - __bfloat162float(__high2bfloat16(hb));
                        aph[half * 2 + rh] = hp;
                        apl[half * 2 + rh] = pack_bf16x2(r0, r1);
                    }
                }
#pragma unroll
                for (int g = 0; g < 8; g++) {
                    int rowv = kt * 16 + (lane & 15);
                    uint32_t voff = f_off(rowv, g * 2 + (lane >> 4));
                    uint32_t vh4[4], vl4[4];
                    ldsm_x4_t(vh4, st + F_VH + voff);
                    ldsm_x4_t(vl4, st + F_VL + voff);
                    mma_bf16(o[2 * g], aph, &vh4[0]);
                    mma_bf16(o[2 * g], aph, &vl4[0]);
                    mma_bf16(o[2 * g], apl, &vh4[0]);
                    mma_bf16(o[2 * g + 1], aph, &vh4[2]);
                    mma_bf16(o[2 * g + 1], aph, &vl4[2]);
                    mma_bf16(o[2 * g + 1], apl, &vh4[2]);
                }
            }
        }
        __syncthreads();
    }

    // ---- epilogue: normalize, split to bf16 hi/lo, store ----
    float iv0 = 1.f / l0, iv1 = 1.f / l1;
    size_t base0 = ((size_t)(b * SEQ) + rr0) * DMODEL + h * HD;
    size_t base1 = base0 + (size_t)8 * DMODEL;
#pragma unroll
    for (int nt = 0; nt < 16; nt++) {
        int d = nt * 8 + (lane & 3) * 2;
        float v0 = o[nt][0] * iv0, v1 = o[nt][1] * iv0;
        float v2 = o[nt][2] * iv1, v3 = o[nt][3] * iv1;
        uint32_t hi0 = pack_bf16x2(v0, v1);
        uint32_t hi1 = pack_bf16x2(v2, v3);
        __nv_bfloat162 hb0, hb1;
        memcpy(&hb0, &hi0, 4);
        memcpy(&hb1, &hi1, 4);
        uint32_t lo0 = pack_bf16x2(v0 - __bfloat162float(__low2bfloat16(hb0)),
                                   v1 - __bfloat162float(__high2bfloat16(hb0)));
        uint32_t lo1 = pack_bf16x2(v2 - __bfloat162float(__low2bfloat16(hb1)),
                                   v3 - __bfloat162float(__high2bfloat16(hb1)));
        *(uint32_t*)(yhi + base0 + d) = hi0;
        *(uint32_t*)(ylo + base0 + d) = lo0;
        *(uint32_t*)(yhi + base1 + d) = hi1;
        *(uint32_t*)(ylo + base1 + d) = lo1;
    }
}

// ---------------------------------------------------------------------------
extern "C" void kernel_launch(void* const* d_in, const int* in_sizes, int n_in,
                              void* d_out, int out_size) {
    const float* x     = (const float*)d_in[0];
    const float* Wq    = (const float*)d_in[1];
    const float* Wk    = (const float*)d_in[2];
    const float* Wv    = (const float*)d_in[3];
    const float* Wproj = (const float*)d_in[4];
    const float* qgain = (const float*)d_in[5];

    float *qb_, *kb_, *vb_;
    cudaGetSymbolAddress((void**)&qb_, g_q);
    cudaGetSymbolAddress((void**)&kb_, g_k);
    cudaGetSymbolAddress((void**)&vb_, g_v);
    __nv_bfloat16 *xhi, *xlo, *yhi, *ylo, *qh, *ql, *kh, *kl, *vh, *vl;
    __nv_bfloat16 *wqh, *wql, *wkh, *wkl, *wvh, *wvl, *wph, *wpl;
    cudaGetSymbolAddress((void**)&xhi, g_xhi);  cudaGetSymbolAddress((void**)&xlo, g_xlo);
    cudaGetSymbolAddress((void**)&yhi, g_yhi);  cudaGetSymbolAddress((void**)&ylo, g_ylo);
    cudaGetSymbolAddress((void**)&qh, g_qhi);   cudaGetSymbolAddress((void**)&ql, g_qlo);
    cudaGetSymbolAddress((void**)&kh, g_khi);   cudaGetSymbolAddress((void**)&kl, g_klo);
    cudaGetSymbolAddress((void**)&vh, g_vhi);   cudaGetSymbolAddress((void**)&vl, g_vlo);
    cudaGetSymbolAddress((void**)&wqh, g_wqhi); cudaGetSymbolAddress((void**)&wql, g_wqlo);
    cudaGetSymbolAddress((void**)&wkh, g_wkhi); cudaGetSymbolAddress((void**)&wkl, g_wklo);
    cudaGetSymbolAddress((void**)&wvh, g_wvhi); cudaGetSymbolAddress((void**)&wvl, g_wvlo);
    cudaGetSymbolAddress((void**)&wph, g_wphi); cudaGetSymbolAddress((void**)&wpl, g_wplo);

    cudaFuncSetAttribute(gemm_bf16x3, cudaFuncAttributeMaxDynamicSharedMemorySize, GSMEM_TOTAL);
    cudaFuncSetAttribute(flash_mma, cudaFuncAttributeMaxDynamicSharedMemorySize, FSMEM_TOTAL);

    rope_table_kernel<<<SEQ, 64>>>();

    {
        int n4 = BS * DMODEL / 4;
        split_kernel<<<(n4 + 255) / 256, 256>>>((const float4*)x, (__nv_bfloat162*)xhi, (__nv_bfloat162*)xlo, n4);
        n4 = DMODEL * DMODEL / 4;
        split_kernel<<<(n4 + 255) / 256, 256>>>((const float4*)Wq, (__nv_bfloat162*)wqh, (__nv_bfloat162*)wql, n4);
        split_kernel<<<(n4 + 255) / 256, 256>>>((const float4*)Wproj, (__nv_bfloat162*)wph, (__nv_bfloat162*)wpl, n4);
        n4 = KVD * DMODEL / 4;
        split_kernel<<<(n4 + 255) / 256, 256>>>((const float4*)Wk, (__nv_bfloat162*)wkh, (__nv_bfloat162*)wkl, n4);
        split_kernel<<<(n4 + 255) / 256, 256>>>((const float4*)Wv, (__nv_bfloat162*)wvh, (__nv_bfloat162*)wvl, n4);
    }

    gemm_bf16x3<<<dim3(DMODEL / 128, BS / 128), 256, GSMEM_TOTAL>>>(xhi, xlo, wqh, wql, qb_, BS, DMODEL, DMODEL);
    gemm_bf16x3<<<dim3(KVD / 128, BS / 128), 256, GSMEM_TOTAL>>>(xhi, xlo, wkh, wkl, kb_, BS, KVD, DMODEL);
    gemm_bf16x3<<<dim3(KVD / 128, BS / 128), 256, GSMEM_TOTAL>>>(xhi, xlo, wvh, wvl, vb_, BS, KVD, DMODEL);

    rmsnorm_rope_split<<<dim3(BS, NH), HD>>>(qb_, qh, ql, qgain, NH, 0.08838834764831845f);
    rmsnorm_rope_split<<<dim3(BS, NKV), HD>>>(kb_, kh, kl, nullptr, NKV, 1.0f);
    {
        int n4 = BS * KVD / 4;
        split_kernel<<<(n4 + 255) / 256, 256>>>((const float4*)vb_, (__nv_bfloat162*)vh, (__nv_bfloat162*)vl, n4);
    }

    flash_mma<<<dim3(SEQ / FBQ, BATCH * NH), 256, FSMEM_TOTAL>>>(qh, ql, kh, kl, vh, vl, yhi, ylo);

    gemm_bf16x3<<<dim3(DMODEL / 128, BS / 128), 256, GSMEM_TOTAL>>>(yhi, ylo, wph, wpl, (float*)d_out, BS, DMODEL, DMODEL);
}

// round 6
// speedup vs baseline: 3.7460x; 1.7057x over previous
#include <cuda_runtime.h>
#include <cuda_bf16.h>
#include <math.h>
#include <stdint.h>
#include <string.h>

#define BATCH 2
#define SEQ 2048
#define DMODEL 2048
#define NH 16
#define NKV 4
#define HD 128
#define BS (BATCH*SEQ)
#define KVD (NKV*HD)
#define NQKV (DMODEL + 2*KVD)     // 3072
#define LOG2E 1.4426950408889634f

// ---------------- scratch (__device__ globals; no allocs allowed) ----------
__device__ float g_qkv[(size_t)BS*NQKV];
__device__ float g_cos[SEQ*64];
__device__ float g_sin[SEQ*64];

__device__ __nv_bfloat16 g_xhi[(size_t)BS*DMODEL];
__device__ __nv_bfloat16 g_xlo[(size_t)BS*DMODEL];
__device__ __nv_bfloat16 g_yhi[(size_t)BS*DMODEL];
__device__ __nv_bfloat16 g_ylo[(size_t)BS*DMODEL];
__device__ __nv_bfloat16 g_qhi[(size_t)BS*DMODEL];
__device__ __nv_bfloat16 g_qlo[(size_t)BS*DMODEL];
__device__ __nv_bfloat16 g_khi[(size_t)BS*KVD];
__device__ __nv_bfloat16 g_klo[(size_t)BS*KVD];
__device__ __nv_bfloat16 g_vhi[(size_t)BS*KVD];
__device__ __nv_bfloat16 g_vlo[(size_t)BS*KVD];
__device__ __nv_bfloat16 g_wchi[(size_t)NQKV*DMODEL];   // [Wq;Wk;Wv] rows
__device__ __nv_bfloat16 g_wclo[(size_t)NQKV*DMODEL];
__device__ __nv_bfloat16 g_wphi[(size_t)DMODEL*DMODEL];
__device__ __nv_bfloat16 g_wplo[(size_t)DMODEL*DMODEL];

// ---------------- mma.sync helpers -----------------------------------------
__device__ __forceinline__ uint32_t smem_u32(const void* p) {
    uint32_t a;
    asm("{ .reg .u64 t; cvta.to.shared.u64 t, %1; cvt.u32.u64 %0, t; }" : "=r"(a) : "l"(p));
    return a;
}
__device__ __forceinline__ void ldsm_x4(uint32_t* r, uint32_t addr) {
    asm volatile("ldmatrix.sync.aligned.m8n8.x4.shared.b16 {%0,%1,%2,%3}, [%4];"
                 : "=r"(r[0]), "=r"(r[1]), "=r"(r[2]), "=r"(r[3]) : "r"(addr));
}
__device__ __forceinline__ void ldsm_x4_t(uint32_t* r, uint32_t addr) {
    asm volatile("ldmatrix.sync.aligned.m8n8.x4.trans.shared.b16 {%0,%1,%2,%3}, [%4];"
                 : "=r"(r[0]), "=r"(r[1]), "=r"(r[2]), "=r"(r[3]) : "r"(addr));
}
__device__ __forceinline__ void mma_bf16(float* d, const uint32_t* a, const uint32_t* b) {
    asm volatile("mma.sync.aligned.m16n8k16.row.col.f32.bf16.bf16.f32 "
                 "{%0,%1,%2,%3}, {%4,%5,%6,%7}, {%8,%9}, {%0,%1,%2,%3};"
                 : "+f"(d[0]), "+f"(d[1]), "+f"(d[2]), "+f"(d[3])
                 : "r"(a[0]), "r"(a[1]), "r"(a[2]), "r"(a[3]), "r"(b[0]), "r"(b[1]));
}
__device__ __forceinline__ uint32_t pack_bf16x2(float v0, float v1) {
    uint32_t r;
    asm("cvt.rn.bf16x2.f32 %0, %1, %2;" : "=r"(r) : "f"(v1), "f"(v0));
    return r;
}
#define CP_ASYNC16(s, g) \
    asm volatile("cp.async.cg.shared.global [%0], [%1], 16;" :: "r"(s), "l"(g))

// ---------------- fp32 -> bf16 hi/lo split ---------------------------------
__global__ __launch_bounds__(256) void split_kernel(const float4* __restrict__ src,
                                                    __nv_bfloat162* __restrict__ hi,
                                                    __nv_bfloat162* __restrict__ lo,
                                                    int n4) {
    int i = blockIdx.x * blockDim.x + threadIdx.x;
    if (i >= n4) return;
    float4 v = src[i];
    __nv_bfloat16 h0 = __float2bfloat16(v.x), h1 = __float2bfloat16(v.y);
    __nv_bfloat16 h2 = __float2bfloat16(v.z), h3 = __float2bfloat16(v.w);
    hi[2 * i + 0] = __halves2bfloat162(h0, h1);
    hi[2 * i + 1] = __halves2bfloat162(h2, h3);
    lo[2 * i + 0] = __halves2bfloat162(__float2bfloat16(v.x - __bfloat162float(h0)),
                                       __float2bfloat16(v.y - __bfloat162float(h1)));
    lo[2 * i + 1] = __halves2bfloat162(__float2bfloat16(v.z - __bfloat162float(h2)),
                                       __float2bfloat16(v.w - __bfloat162float(h3)));
}

// strided split: rows x cols (cols mult of 4) out of a wider row of rstride
__global__ __launch_bounds__(256) void split_strided(const float* __restrict__ src,
                                                     __nv_bfloat162* __restrict__ hi,
                                                     __nv_bfloat162* __restrict__ lo,
                                                     int rows, int cols, int rstride, int coloff) {
    int i = blockIdx.x * blockDim.x + threadIdx.x;
    int c4 = cols / 4;
    if (i >= rows * c4) return;
    int row = i / c4, cc = (i % c4) * 4;
    float4 v = *(const float4*)(src + (size_t)row * rstride + coloff + cc);
    __nv_bfloat16 h0 = __float2bfloat16(v.x), h1 = __float2bfloat16(v.y);
    __nv_bfloat16 h2 = __float2bfloat16(v.z), h3 = __float2bfloat16(v.w);
    size_t o = ((size_t)row * cols + cc) / 2;
    hi[o + 0] = __halves2bfloat162(h0, h1);
    hi[o + 1] = __halves2bfloat162(h2, h3);
    lo[o + 0] = __halves2bfloat162(__float2bfloat16(v.x - __bfloat162float(h0)),
                                   __float2bfloat16(v.y - __bfloat162float(h1)));
    lo[o + 1] = __halves2bfloat162(__float2bfloat16(v.z - __bfloat162float(h2)),
                                   __float2bfloat16(v.w - __bfloat162float(h3)));
}

// ---------------- bf16x3 mma.sync GEMM: C[M,N] = A[M,K] @ B[N,K]^T ---------
// 128x128 CTA tile, BK=32, 3-stage cp.async pipeline, 256 threads, 2 CTAs/SM
#define GSTAGES 3
#define GBK 32
#define GTILEB (128*GBK*2)
#define GSTAGEB (4*GTILEB)
#define GSMEM_TOTAL (GSTAGES*GSTAGEB)

__device__ __forceinline__ uint32_t sw_off(int row, int chunk) {
    return (uint32_t)(row * 64 + ((chunk ^ (row & 3)) << 4));
}
__device__ __forceinline__ void g_load_stage(const __nv_bfloat16* Ahi, const __nv_bfloat16* Alo,
                                             const __nv_bfloat16* Bhi, const __nv_bfloat16* Blo,
                                             int bm, int bn, int K, int kc,
                                             uint32_t tb, int tid) {
    size_t kcol = (size_t)kc * GBK;
#pragma unroll
    for (int j = 0; j < 2; j++) {
        int idx = tid + j * 256;
        int row = idx >> 2, c = idx & 3;
        uint32_t so = sw_off(row, c);
        size_t ga = (size_t)(bm + row) * K + kcol + c * 8;
        size_t gb = (size_t)(bn + row) * K + kcol + c * 8;
        CP_ASYNC16(tb + so, Ahi + ga);
        CP_ASYNC16(tb + GTILEB + so, Alo + ga);
        CP_ASYNC16(tb + 2 * GTILEB + so, Bhi + gb);
        CP_ASYNC16(tb + 3 * GTILEB + so, Blo + gb);
    }
}

__global__ __launch_bounds__(256, 2) void gemm_bf16x3(
    const __nv_bfloat16* __restrict__ Ahi, const __nv_bfloat16* __restrict__ Alo,
    const __nv_bfloat16* __restrict__ Bhi, const __nv_bfloat16* __restrict__ Blo,
    float* __restrict__ C, int M, int N, int K) {
    extern __shared__ char smem[];
    uint32_t sb = smem_u32(smem);
    int tid = threadIdx.x, wid = tid >> 5, lane = tid & 31;
    int bm = blockIdx.y * 128, bn = blockIdx.x * 128;
    int wm = (wid >> 2) * 64;
    int wn = (wid & 3) * 32;
    const int NK = K / GBK;

    float acc[4][4][4];
#pragma unroll
    for (int a = 0; a < 4; a++)
#pragma unroll
        for (int b = 0; b < 4; b++)
#pragma unroll
            for (int c = 0; c < 4; c++) acc[a][b][c] = 0.f;

#pragma unroll
    for (int s = 0; s < GSTAGES - 1; s++) {
        g_load_stage(Ahi, Alo, Bhi, Blo, bm, bn, K, s, sb + s * GSTAGEB, tid);
        asm volatile("cp.async.commit_group;" ::: "memory");
    }

    for (int kc = 0; kc < NK; kc++) {
        asm volatile("cp.async.wait_group %0;" :: "n"(GSTAGES - 2) : "memory");
        __syncthreads();
        uint32_t tb = sb + (kc % GSTAGES) * GSTAGEB;

#pragma unroll
        for (int ks = 0; ks < 2; ks++) {
            uint32_t ah[4][4], al[4][4], bh[2][4], bl[2][4];
#pragma unroll
            for (int mt = 0; mt < 4; mt++) {
                int row = wm + mt * 16 + (lane & 15);
                uint32_t off = sw_off(row, ks * 2 + (lane >> 4));
                ldsm_x4(ah[mt], tb + off);
                ldsm_x4(al[mt], tb + GTILEB + off);
            }
#pragma unroll
            for (int pr = 0; pr < 2; pr++) {
                int row = wn + pr * 16 + (lane & 7) + ((lane >> 4) << 3);
                uint32_t off = sw_off(row, ks * 2 + ((lane >> 3) & 1));
                ldsm_x4(bh[pr], tb + 2 * GTILEB + off);
                ldsm_x4(bl[pr], tb + 3 * GTILEB + off);
            }
#pragma unroll
            for (int mt = 0; mt < 4; mt++)
#pragma unroll
                for (int nt = 0; nt < 4; nt++) {
                    const uint32_t* bhp = &bh[nt >> 1][(nt & 1) * 2];
                    const uint32_t* blp = &bl[nt >> 1][(nt & 1) * 2];
                    mma_bf16(acc[mt][nt], ah[mt], bhp);
                    mma_bf16(acc[mt][nt], ah[mt], blp);
                    mma_bf16(acc[mt][nt], al[mt], bhp);
                }
        }
        __syncthreads();
        if (kc + GSTAGES - 1 < NK) {
            int pst = (kc + GSTAGES - 1) % GSTAGES;
            g_load_stage(Ahi, Alo, Bhi, Blo, bm, bn, K, kc + GSTAGES - 1, sb + pst * GSTAGEB, tid);
        }
        asm volatile("cp.async.commit_group;" ::: "memory");
    }

#pragma unroll
    for (int mt = 0; mt < 4; mt++) {
        int row0 = bm + wm + mt * 16 + (lane >> 2);
#pragma unroll
        for (int nt = 0; nt < 4; nt++) {
            int col = bn + wn + nt * 8 + (lane & 3) * 2;
            *(float2*)(C + (size_t)row0 * N + col) = make_float2(acc[mt][nt][0], acc[mt][nt][1]);
            *(float2*)(C + (size_t)(row0 + 8) * N + col) = make_float2(acc[mt][nt][2], acc[mt][nt][3]);
        }
    }
}

// ---------------- RoPE table ------------------------------------------------
__global__ void rope_table_kernel() {
    int i = threadIdx.x;
    int t = blockIdx.x;
    double inv = exp(-((double)(2 * i) / 128.0) * log(10000.0));
    double a = (double)t * inv;
    g_cos[t * 64 + i] = (float)cos(a);
    g_sin[t * 64 + i] = (float)sin(a);
}

// ---------------- fused RMSNorm + RoPE -> bf16 hi/lo ------------------------
// reads from g_qkv with row stride NQKV at column offset coloff
__global__ __launch_bounds__(128) void rmsnorm_rope_split(const float* __restrict__ src,
                                                          int coloff,
                                                          __nv_bfloat16* __restrict__ dhi,
                                                          __nv_bfloat16* __restrict__ dlo,
                                                          const float* __restrict__ gain,
                                                          int nheads, float outscale) {
    int token = blockIdx.x;
    int h = blockIdx.y;
    int d = threadIdx.x;
    int s = token & (SEQ - 1);
    float v = src[(size_t)token * NQKV + coloff + h * HD + d];

    float ss = v * v;
#pragma unroll
    for (int o = 16; o; o >>= 1) ss += __shfl_xor_sync(0xffffffffu, ss, o);
    __shared__ float ws[4];
    int lane = d & 31, w = d >> 5;
    if (lane == 0) ws[w] = ss;
    __syncthreads();
    float tot = ws[0] + ws[1] + ws[2] + ws[3];
    float inv = rsqrtf(tot * (1.0f / HD) + 1.1920928955078125e-7f);
    v *= inv;

    __shared__ float sv[HD];
    sv[d] = v;
    __syncthreads();

    float out;
    if (d < 64) {
        float c = g_cos[s * 64 + d], si = g_sin[s * 64 + d];
        out = v * c + sv[d + 64] * si;
    } else {
        int i = d - 64;
        float c = g_cos[s * 64 + i], si = g_sin[s * 64 + i];
        out = -sv[i] * si + v * c;
    }
    if (gain) out *= gain[h] * outscale;
    size_t idx = ((size_t)token * nheads + h) * HD + d;
    __nv_bfloat16 hv = __float2bfloat16(out);
    dhi[idx] = hv;
    dlo[idx] = __float2bfloat16(out - __bfloat162float(hv));
}

// ---------------- tensor-core flash attention (causal, GQA, bf16x3) ---------
#define FBQ 128
#define FBK 64
#define F_QHI 0
#define F_QLO 32768
#define F_STAGE0 65536
#define F_STAGEB 65536
#define F_KH 0
#define F_KL 16384
#define F_VH 32768
#define F_VL 49152
#define FSMEM_TOTAL (65536 + 2*F_STAGEB)

__device__ __forceinline__ uint32_t f_off(int row, int chunk) {
    return (uint32_t)(row * 256 + ((chunk ^ (row & 7)) << 4));
}

__device__ __forceinline__ void f_load_kv(uint32_t st,
                                          const __nv_bfloat16* kh, const __nv_bfloat16* kl,
                                          const __nv_bfloat16* vh, const __nv_bfloat16* vl,
                                          size_t gbase, int tid) {
#pragma unroll
    for (int j = 0; j < 4; j++) {
        int id = tid + j * 256;
        int row = id >> 4, c = id & 15;
        uint32_t so = f_off(row, c);
        size_t g = gbase + (size_t)row * KVD + c * 8;
        CP_ASYNC16(st + F_KH + so, kh + g);
        CP_ASYNC16(st + F_KL + so, kl + g);
        CP_ASYNC16(st + F_VH + so, vh + g);
        CP_ASYNC16(st + F_VL + so, vl + g);
    }
}

__global__ __launch_bounds__(256, 1) void flash_mma(
    const __nv_bfloat16* __restrict__ qh, const __nv_bfloat16* __restrict__ ql,
    const __nv_bfloat16* __restrict__ kh, const __nv_bfloat16* __restrict__ kl,
    const __nv_bfloat16* __restrict__ vh, const __nv_bfloat16* __restrict__ vl,
    __nv_bfloat16* __restrict__ yhi, __nv_bfloat16* __restrict__ ylo) {
    extern __shared__ char smem[];
    uint32_t sb = smem_u32(smem);
    int tid = threadIdx.x, lane = tid & 31, w = tid >> 5;
    int bh_ = blockIdx.y;
    int b = bh_ >> 4, h = bh_ & 15, hkv = h >> 2;
    int qb = blockIdx.x * FBQ;
    int q0 = w * 16;

#pragma unroll
    for (int j = 0; j < 8; j++) {
        int id = tid + j * 256;
        int row = id >> 4, c = id & 15;
        uint32_t so = f_off(row, c);
        size_t g = ((size_t)(b * SEQ + qb + row)) * DMODEL + h * HD + c * 8;
        CP_ASYNC16(sb + F_QHI + so, qh + g);
        CP_ASYNC16(sb + F_QLO + so, ql + g);
    }
    asm volatile("cp.async.commit_group;" ::: "memory");

    size_t kvhead = (size_t)(b * SEQ) * KVD + hkv * HD;
    int ntiles = qb / FBK + 2;

    f_load_kv(sb + F_STAGE0, kh, kl, vh, vl, kvhead, tid);
    asm volatile("cp.async.commit_group;" ::: "memory");

    float o[16][4];
#pragma unroll
    for (int nt = 0; nt < 16; nt++)
#pragma unroll
        for (int e = 0; e < 4; e++) o[nt][e] = 0.f;
    float m0 = -1e30f, m1 = -1e30f, l0 = 0.f, l1 = 0.f;

    int qmax = qb + q0 + 15;
    int rr0 = qb + q0 + (lane >> 2);
    int rr1 = rr0 + 8;

    for (int t = 0; t < ntiles; t++) {
        if (t + 1 < ntiles)
            f_load_kv(sb + F_STAGE0 + ((t + 1) & 1) * F_STAGEB, kh, kl, vh, vl,
                      kvhead + (size_t)(t + 1) * FBK * KVD, tid);
        asm volatile("cp.async.commit_group;" ::: "memory");
        asm volatile("cp.async.wait_group 1;" ::: "memory");
        __syncthreads();

        int kv = t * FBK;
        if (kv <= qmax) {
            uint32_t st = sb + F_STAGE0 + (t & 1) * F_STAGEB;

            float c[8][4];
#pragma unroll
            for (int nt = 0; nt < 8; nt++)
#pragma unroll
                for (int e = 0; e < 4; e++) c[nt][e] = 0.f;

#pragma unroll
            for (int ds = 0; ds < 8; ds++) {
                uint32_t qoff = f_off(q0 + (lane & 15), ds * 2 + (lane >> 4));
                uint32_t ah4[4], al4[4];
                ldsm_x4(ah4, sb + F_QHI + qoff);
                ldsm_x4(al4, sb + F_QLO + qoff);
                uint32_t bh4[4][4], bl4[4][4];
#pragma unroll
                for (int g = 0; g < 4; g++) {
                    int rowk = g * 16 + (lane & 7) + ((lane >> 4) << 3);
                    uint32_t koff = f_off(rowk, ds * 2 + ((lane >> 3) & 1));
                    ldsm_x4(bh4[g], st + F_KH + koff);
                    ldsm_x4(bl4[g], st + F_KL + koff);
                }
#pragma unroll
                for (int g = 0; g < 4; g++)
#pragma unroll
                    for (int sub = 0; sub < 2; sub++) {
                        int nt = g * 2 + sub;
                        mma_bf16(c[nt], ah4, &bh4[g][sub * 2]);
                        mma_bf16(c[nt], ah4, &bl4[g][sub * 2]);
                        mma_bf16(c[nt], al4, &bh4[g][sub * 2]);
                    }
            }

            if (kv + FBK - 1 > qb + q0) {
#pragma unroll
                for (int nt = 0; nt < 8; nt++) {
                    int col = kv + nt * 8 + (lane & 3) * 2;
                    if (col > rr0) c[nt][0] = -1e30f;
                    if (col + 1 > rr0) c[nt][1] = -1e30f;
                    if (col > rr1) c[nt][2] = -1e30f;
                    if (col + 1 > rr1) c[nt][3] = -1e30f;
                }
            }

            float mx0 = -1e30f, mx1 = -1e30f;
#pragma unroll
            for (int nt = 0; nt < 8; nt++) {
                mx0 = fmaxf(mx0, fmaxf(c[nt][0], c[nt][1]));
                mx1 = fmaxf(mx1, fmaxf(c[nt][2], c[nt][3]));
            }
            mx0 = fmaxf(mx0, __shfl_xor_sync(0xffffffffu, mx0, 1));
            mx0 = fmaxf(mx0, __shfl_xor_sync(0xffffffffu, mx0, 2));
            mx1 = fmaxf(mx1, __shfl_xor_sync(0xffffffffu, mx1, 1));
            mx1 = fmaxf(mx1, __shfl_xor_sync(0xffffffffu, mx1, 2));
            float m0n = fmaxf(m0, mx0), m1n = fmaxf(m1, mx1);
            float rs0 = exp2f((m0 - m0n) * LOG2E);
            float rs1 = exp2f((m1 - m1n) * LOG2E);
            float s0 = 0.f, s1 = 0.f;
#pragma unroll
            for (int nt = 0; nt < 8; nt++) {
                c[nt][0] = exp2f((c[nt][0] - m0n) * LOG2E);
                c[nt][1] = exp2f((c[nt][1] - m0n) * LOG2E);
                c[nt][2] = exp2f((c[nt][2] - m1n) * LOG2E);
                c[nt][3] = exp2f((c[nt][3] - m1n) * LOG2E);
                s0 += c[nt][0] + c[nt][1];
                s1 += c[nt][2] + c[nt][3];
            }
            s0 += __shfl_xor_sync(0xffffffffu, s0, 1);
            s0 += __shfl_xor_sync(0xffffffffu, s0, 2);
            s1 += __shfl_xor_sync(0xffffffffu, s1, 1);
            s1 += __shfl_xor_sync(0xffffffffu, s1, 2);
            l0 = l0 * rs0 + s0;
            l1 = l1 * rs1 + s1;
            m0 = m0n; m1 = m1n;
#pragma unroll
            for (int nt = 0; nt < 16; nt++) {
                o[nt][0] *= rs0; o[nt][1] *= rs0;
                o[nt][2] *= rs1; o[nt][3] *= rs1;
            }

#pragma unroll
            for (int kt = 0; kt < 4; kt++) {
                uint32_t aph[4], apl[4];
#pragma unroll
                for (int half = 0; half < 2; half++) {
                    const float* cc = c[2 * kt + half];
#pragma unroll
                    for (int rh = 0; rh < 2; rh++) {
                        float v0 = cc[rh * 2], v1 = cc[rh * 2 + 1];
                        uint32_t hp = pack_bf16x2(v0, v1);
                        __nv_bfloat162 hb;
                        memcpy(&hb, &hp, 4);
                        float r0 = v0 - __bfloat162float(__low2bfloat16(hb));
                        float r1 = v1 - __bfloat162float(__high2bfloat16(hb));
                        aph[half * 2 + rh] = hp;
                        apl[half * 2 + rh] = pack_bf16x2(r0, r1);
                    }
                }
#pragma unroll
                for (int g = 0; g < 8; g++) {
                    int rowv = kt * 16 + (lane & 15);
                    uint32_t voff = f_off(rowv, g * 2 + (lane >> 4));
                    uint32_t vh4[4], vl4[4];
                    ldsm_x4_t(vh4, st + F_VH + voff);
                    ldsm_x4_t(vl4, st + F_VL + voff);
                    mma_bf16(o[2 * g], aph, &vh4[0]);
                    mma_bf16(o[2 * g], aph, &vl4[0]);
                    mma_bf16(o[2 * g], apl, &vh4[0]);
                    mma_bf16(o[2 * g + 1], aph, &vh4[2]);
                    mma_bf16(o[2 * g + 1], aph, &vl4[2]);
                    mma_bf16(o[2 * g + 1], apl, &vh4[2]);
                }
            }
        }
        __syncthreads();
    }

    float iv0 = 1.f / l0, iv1 = 1.f / l1;
    size_t base0 = ((size_t)(b * SEQ) + rr0) * DMODEL + h * HD;
    size_t base1 = base0 + (size_t)8 * DMODEL;
#pragma unroll
    for (int nt = 0; nt < 16; nt++) {
        int d = nt * 8 + (lane & 3) * 2;
        float v0 = o[nt][0] * iv0, v1 = o[nt][1] * iv0;
        float v2 = o[nt][2] * iv1, v3 = o[nt][3] * iv1;
        uint32_t hi0 = pack_bf16x2(v0, v1);
        uint32_t hi1 = pack_bf16x2(v2, v3);
        __nv_bfloat162 hb0, hb1;
        memcpy(&hb0, &hi0, 4);
        memcpy(&hb1, &hi1, 4);
        uint32_t lo0 = pack_bf16x2(v0 - __bfloat162float(__low2bfloat16(hb0)),
                                   v1 - __bfloat162float(__high2bfloat16(hb0)));
        uint32_t lo1 = pack_bf16x2(v2 - __bfloat162float(__low2bfloat16(hb1)),
                                   v3 - __bfloat162float(__high2bfloat16(hb1)));
        *(uint32_t*)(yhi + base0 + d) = hi0;
        *(uint32_t*)(ylo + base0 + d) = lo0;
        *(uint32_t*)(yhi + base1 + d) = hi1;
        *(uint32_t*)(ylo + base1 + d) = lo1;
    }
}

// ---------------------------------------------------------------------------
extern "C" void kernel_launch(void* const* d_in, const int* in_sizes, int n_in,
                              void* d_out, int out_size) {
    const float* x     = (const float*)d_in[0];
    const float* Wq    = (const float*)d_in[1];
    const float* Wk    = (const float*)d_in[2];
    const float* Wv    = (const float*)d_in[3];
    const float* Wproj = (const float*)d_in[4];
    const float* qgain = (const float*)d_in[5];

    float* qkv;
    cudaGetSymbolAddress((void**)&qkv, g_qkv);
    __nv_bfloat16 *xhi, *xlo, *yhi, *ylo, *qh, *ql, *kh, *kl, *vh, *vl;
    __nv_bfloat16 *wch, *wcl, *wph, *wpl;
    cudaGetSymbolAddress((void**)&xhi, g_xhi);  cudaGetSymbolAddress((void**)&xlo, g_xlo);
    cudaGetSymbolAddress((void**)&yhi, g_yhi);  cudaGetSymbolAddress((void**)&ylo, g_ylo);
    cudaGetSymbolAddress((void**)&qh, g_qhi);   cudaGetSymbolAddress((void**)&ql, g_qlo);
    cudaGetSymbolAddress((void**)&kh, g_khi);   cudaGetSymbolAddress((void**)&kl, g_klo);
    cudaGetSymbolAddress((void**)&vh, g_vhi);   cudaGetSymbolAddress((void**)&vl, g_vlo);
    cudaGetSymbolAddress((void**)&wch, g_wchi); cudaGetSymbolAddress((void**)&wcl, g_wclo);
    cudaGetSymbolAddress((void**)&wph, g_wphi); cudaGetSymbolAddress((void**)&wpl, g_wplo);

    cudaFuncSetAttribute(gemm_bf16x3, cudaFuncAttributeMaxDynamicSharedMemorySize, GSMEM_TOTAL);
    cudaFuncSetAttribute(flash_mma, cudaFuncAttributeMaxDynamicSharedMemorySize, FSMEM_TOTAL);

    rope_table_kernel<<<SEQ, 64>>>();

    // splits: x, and [Wq;Wk;Wv] into one combined weight buffer, Wproj
    {
        int n4 = BS * DMODEL / 4;
        split_kernel<<<(n4 + 255) / 256, 256>>>((const float4*)x, (__nv_bfloat162*)xhi, (__nv_bfloat162*)xlo, n4);
        n4 = DMODEL * DMODEL / 4;
        split_kernel<<<(n4 + 255) / 256, 256>>>((const float4*)Wq,
            (__nv_bfloat162*)wch, (__nv_bfloat162*)wcl, n4);
        split_kernel<<<(n4 + 255) / 256, 256>>>((const float4*)Wproj,
            (__nv_bfloat162*)wph, (__nv_bfloat162*)wpl, n4);
        n4 = KVD * DMODEL / 4;
        size_t offk = (size_t)DMODEL * DMODEL;           // elements
        size_t offv = offk + (size_t)KVD * DMODEL;
        split_kernel<<<(n4 + 255) / 256, 256>>>((const float4*)Wk,
            (__nv_bfloat162*)(wch + offk), (__nv_bfloat162*)(wcl + offk), n4);
        split_kernel<<<(n4 + 255) / 256, 256>>>((const float4*)Wv,
            (__nv_bfloat162*)(wch + offv), (__nv_bfloat162*)(wcl + offv), n4);
    }

    // one fused QKV projection: [4096 x 3072]
    gemm_bf16x3<<<dim3(NQKV / 128, BS / 128), 256, GSMEM_TOTAL>>>(
        xhi, xlo, wch, wcl, qkv, BS, NQKV, DMODEL);

    rmsnorm_rope_split<<<dim3(BS, NH), HD>>>(qkv, 0, qh, ql, qgain, NH, 0.08838834764831845f);
    rmsnorm_rope_split<<<dim3(BS, NKV), HD>>>(qkv, DMODEL, kh, kl, nullptr, NKV, 1.0f);
    {
        int n = BS * KVD / 4;
        split_strided<<<(n + 255) / 256, 256>>>(qkv, (__nv_bfloat162*)vh, (__nv_bfloat162*)vl,
                                                BS, KVD, NQKV, DMODEL + KVD);
    }

    flash_mma<<<dim3(SEQ / FBQ, BATCH * NH), 256, FSMEM_TOTAL>>>(qh, ql, kh, kl, vh, vl, yhi, ylo);

    gemm_bf16x3<<<dim3(DMODEL / 128, BS / 128), 256, GSMEM_TOTAL>>>(
        yhi, ylo, wph, wpl, (float*)d_out, BS, DMODEL, DMODEL);
}